// round 1
// baseline (speedup 1.0000x reference)
#include <cuda_runtime.h>
#include <cuda_bf16.h>
#include <math.h>

#define B 32
#define P 32768
#define O 32
#define NCH 16          // chunks per batch in match kernel (P / 2048)
#define PPB 2048        // priors per block (256 threads * 8)
#define THRESH 0.35f

// ---------------- scratch (static device globals; no allocation) ----------------
__device__ float g_bt_iou[B * P];     // best-truth IoU per (b,p) (post-fix)
__device__ int   g_bt_idx[B * P];     // best-truth index per (b,p) (post-fix)
__device__ float g_mine [B * P];      // pos ? 0 : ce
__device__ float g_bp_i [B * O * NCH];
__device__ float g_bp_u [B * O * NCH];
__device__ int   g_bp_p [B * O * NCH];
__device__ int    g_num_pos[B];
__device__ double g_loss_l;
__device__ double g_pos_ce;
__device__ double g_neg_ce;

// ---------------- K0: zero accumulators ----------------
__global__ void init_kernel() {
    int t = threadIdx.x;
    if (t < B) g_num_pos[t] = 0;
    if (t == 0) { g_loss_l = 0.0; g_pos_ce = 0.0; g_neg_ce = 0.0; }
}

// ---------------- K1: match (IoU argmaxes) ----------------
// grid (NCH, B), block 256. Each thread handles 8 priors (stride 256).
__global__ void __launch_bounds__(256) match_kernel(const float* __restrict__ priors,
                                                    const float* __restrict__ targets) {
    const int b     = blockIdx.y;
    const int chunk = blockIdx.x;
    const int tid   = threadIdx.x;
    const int lane  = tid & 31;
    const int wid   = tid >> 5;

    __shared__ float s_tx0[O], s_ty0[O], s_tx1[O], s_ty1[O], s_ta[O];
    __shared__ float s_wi[O][8];
    __shared__ float s_wu[O][8];
    __shared__ int   s_wp[O][8];

    if (tid < O) {
        const float* t = targets + (size_t)(b * O + tid) * 5;
        float x0 = t[0], y0 = t[1], x1 = t[2], y1 = t[3];
        s_tx0[tid] = x0; s_ty0[tid] = y0; s_tx1[tid] = x1; s_ty1[tid] = y1;
        s_ta[tid] = __fmul_rn(__fsub_rn(x1, x0), __fsub_rn(y1, y0));
    }
    __syncthreads();

    const int p0 = chunk * PPB + tid;

    // cache 8 priors in point form + area (area from point-form corners, like reference)
    float px0[8], py0[8], px1[8], py1[8], pa[8];
#pragma unroll
    for (int i = 0; i < 8; ++i) {
        float4 pr = reinterpret_cast<const float4*>(priors)[p0 + i * 256];
        float hw = __fmul_rn(pr.z, 0.5f);
        float hh = __fmul_rn(pr.w, 0.5f);
        px0[i] = __fsub_rn(pr.x, hw);
        py0[i] = __fsub_rn(pr.y, hh);
        px1[i] = __fadd_rn(pr.x, hw);
        py1[i] = __fadd_rn(pr.y, hh);
        pa[i]  = __fmul_rn(__fsub_rn(px1[i], px0[i]), __fsub_rn(py1[i], py0[i]));
    }

    // per-prior running best over o (cross-mult compare; strict > keeps first o)
    float bi[8], bu[8]; int bo[8];
#pragma unroll
    for (int i = 0; i < 8; ++i) { bi[i] = 0.0f; bu[i] = 1.0f; bo[i] = 0; }

    for (int o = 0; o < O; ++o) {
        const float tx0 = s_tx0[o], ty0 = s_ty0[o], tx1 = s_tx1[o], ty1 = s_ty1[o], ta = s_ta[o];
        float ci = -1.0f, cu = 1.0f; int cp = 0x7fffffff;   // per-thread best over p for this o
#pragma unroll
        for (int i = 0; i < 8; ++i) {
            float wx = fmaxf(__fsub_rn(fminf(px1[i], tx1), fmaxf(px0[i], tx0)), 0.0f);
            float wy = fmaxf(__fsub_rn(fminf(py1[i], ty1), fmaxf(py0[i], ty0)), 0.0f);
            float in_ = __fmul_rn(wx, wy);
            float un  = __fsub_rn(__fadd_rn(pa[i], ta), in_);
            // best over o (strict >: first max wins, matching jnp.argmax)
            if (__fmul_rn(in_, bu[i]) > __fmul_rn(bi[i], un)) { bi[i] = in_; bu[i] = un; bo[i] = o; }
            // best over this thread's priors for current o (ascending p; strict > keeps lowest p)
            if (__fmul_rn(in_, cu) > __fmul_rn(ci, un)) { ci = in_; cu = un; cp = p0 + i * 256; }
        }
        // warp argmax over 256 priors (tie -> lower p)
#pragma unroll
        for (int d = 16; d > 0; d >>= 1) {
            float oi = __shfl_down_sync(0xffffffffu, ci, d);
            float ou = __shfl_down_sync(0xffffffffu, cu, d);
            int   op = __shfl_down_sync(0xffffffffu, cp, d);
            float l = __fmul_rn(oi, cu);
            float r = __fmul_rn(ci, ou);
            bool take = (l > r) || (l == r && op < cp);
            if (take) { ci = oi; cu = ou; cp = op; }
        }
        if (lane == 0) { s_wi[o][wid] = ci; s_wu[o][wid] = cu; s_wp[o][wid] = cp; }
    }

    // per-prior results: single IEEE divide for the winner (matches reference rounding)
#pragma unroll
    for (int i = 0; i < 8; ++i) {
        int p = p0 + i * 256;
        g_bt_idx[b * P + p] = bo[i];
        g_bt_iou[b * P + p] = __fdiv_rn(bi[i], bu[i]);
    }

    __syncthreads();
    if (tid < O) {
        int o = tid;
        float ci = s_wi[o][0], cu = s_wu[o][0];
        int   cp = s_wp[o][0];
#pragma unroll
        for (int w = 1; w < 8; ++w) {
            float oi = s_wi[o][w], ou = s_wu[o][w];
            int   op = s_wp[o][w];
            float l = __fmul_rn(oi, cu);
            float r = __fmul_rn(ci, ou);
            if ((l > r) || (l == r && op < cp)) { ci = oi; cu = ou; cp = op; }
        }
        int idx = (b * O + o) * NCH + chunk;
        g_bp_i[idx] = ci; g_bp_u[idx] = cu; g_bp_p[idx] = cp;
    }
}

// ---------------- K2: reduce best-prior per (b,o) + forced-match fix ----------------
// grid B, block O threads.
__global__ void fix_kernel() {
    const int b = blockIdx.x;
    const int o = threadIdx.x;
    __shared__ int s_bpi[O];

    int base = (b * O + o) * NCH;
    float ci = g_bp_i[base], cu = g_bp_u[base];
    int   cp = g_bp_p[base];
#pragma unroll
    for (int c = 1; c < NCH; ++c) {
        float oi = g_bp_i[base + c], ou = g_bp_u[base + c];
        int   op = g_bp_p[base + c];
        float l = __fmul_rn(oi, cu);
        float r = __fmul_rn(ci, ou);
        if ((l > r) || (l == r && op < cp)) { ci = oi; cu = ou; cp = op; }
    }
    s_bpi[o] = cp;
    __syncthreads();
    if (o == 0) {
        // sequential, ascending o: last-wins on duplicate indices (XLA scatter order)
        for (int j = 0; j < O; ++j) {
            int p = s_bpi[j];
            g_bt_idx[b * P + p] = j;
            g_bt_iou[b * P + p] = 2.0f;
        }
    }
}

// ---------------- K3: per-prior losses ----------------
__device__ __forceinline__ float smooth_l1(float d) {
    float ad = fabsf(d);
    return (ad < 1.0f) ? __fmul_rn(__fmul_rn(0.5f, d), d) : __fsub_rn(ad, 0.5f);
}

__global__ void __launch_bounds__(256) loss_kernel(const float* __restrict__ loc,
                                                   const float* __restrict__ conf,
                                                   const float* __restrict__ priors,
                                                   const float* __restrict__ targets) {
    const int b = blockIdx.y;
    const int p = blockIdx.x * 256 + threadIdx.x;
    const int lane = threadIdx.x & 31;

    __shared__ float s_t[O][4];
    __shared__ float s_lab[O];
    if (threadIdx.x < O) {
        const float* t = targets + (size_t)(b * O + threadIdx.x) * 5;
        s_t[threadIdx.x][0] = t[0]; s_t[threadIdx.x][1] = t[1];
        s_t[threadIdx.x][2] = t[2]; s_t[threadIdx.x][3] = t[3];
        s_lab[threadIdx.x]  = t[4];
    }
    __syncthreads();

    const int bp = b * P + p;
    const int o  = g_bt_idx[bp];
    const float iou = g_bt_iou[bp];
    const int ct = (iou < THRESH) ? 0 : ((int)s_lab[o] + 1);
    const bool pos = (ct > 0);

    float2 cd = reinterpret_cast<const float2*>(conf)[bp];
    float m  = fmaxf(cd.x, cd.y);
    float mn = fminf(cd.x, cd.y);
    float lse = __fadd_rn(m, logf(__fadd_rn(1.0f, expf(__fsub_rn(mn, m)))));
    float picked = (ct == 0) ? cd.x : cd.y;
    float ce = __fsub_rn(lse, picked);

    g_mine[bp] = pos ? 0.0f : ce;

    float ll = 0.0f;
    if (pos) {
        float4 pr = reinterpret_cast<const float4*>(priors)[p];
        float mx0 = s_t[o][0], my0 = s_t[o][1], mx1 = s_t[o][2], my1 = s_t[o][3];
        float lt0 = __fdiv_rn(__fsub_rn(__fmul_rn(__fadd_rn(mx0, mx1), 0.5f), pr.x),
                              __fmul_rn(0.1f, pr.z));
        float lt1 = __fdiv_rn(__fsub_rn(__fmul_rn(__fadd_rn(my0, my1), 0.5f), pr.y),
                              __fmul_rn(0.1f, pr.w));
        float lt2 = __fdiv_rn(logf(__fdiv_rn(__fsub_rn(mx1, mx0), pr.z)), 0.2f);
        float lt3 = __fdiv_rn(logf(__fdiv_rn(__fsub_rn(my1, my0), pr.w)), 0.2f);
        float4 ld = reinterpret_cast<const float4*>(loc)[bp];
        ll = __fadd_rn(__fadd_rn(smooth_l1(__fsub_rn(ld.x, lt0)),
                                 smooth_l1(__fsub_rn(ld.y, lt1))),
                       __fadd_rn(smooth_l1(__fsub_rn(ld.z, lt2)),
                                 smooth_l1(__fsub_rn(ld.w, lt3))));
    }
    float pce = pos ? ce : 0.0f;

#pragma unroll
    for (int d = 16; d > 0; d >>= 1) {
        ll  += __shfl_down_sync(0xffffffffu, ll, d);
        pce += __shfl_down_sync(0xffffffffu, pce, d);
    }
    unsigned bal = __ballot_sync(0xffffffffu, pos);
    if (lane == 0) {
        if (ll  != 0.0f) atomicAdd(&g_loss_l, (double)ll);
        if (pce != 0.0f) atomicAdd(&g_pos_ce, (double)pce);
        int cnt = __popc(bal);
        if (cnt) atomicAdd(&g_num_pos[b], cnt);
    }
}

// ---------------- K4: per-batch top-k sum of mine (exact radix select) ----------------
__global__ void __launch_bounds__(256) select_kernel() {
    const int b = blockIdx.x;
    const int tid = threadIdx.x;
    const int lane = tid & 31;
    const int wid  = tid >> 5;

    int np = g_num_pos[b];
    long long kll = (long long)7 * np;
    int k = (kll < (P - 1)) ? (int)kll : (P - 1);
    if (k <= 0) return;

    const float* mine = g_mine + (size_t)b * P;

    __shared__ unsigned s_hist[256];
    __shared__ unsigned s_wsum[8];
    __shared__ unsigned s_selb;
    __shared__ unsigned s_kk2;

    unsigned prefix = 0;
    unsigned kk = (unsigned)k;

    for (int pass = 0; pass < 4; ++pass) {
        const int shift = 24 - 8 * pass;
        s_hist[tid] = 0;
        __syncthreads();
        unsigned himask = (pass == 0) ? 0u : (0xFFFFFFFFu << (shift + 8));
        for (int idx = tid; idx < P; idx += 256) {
            unsigned u = __float_as_uint(mine[idx]);
            if ((u & himask) == prefix) atomicAdd(&s_hist[(u >> shift) & 255u], 1u);
        }
        __syncthreads();
        // suffix-cumulative from top bin
        unsigned v = s_hist[255 - tid];
        unsigned c = v;
#pragma unroll
        for (int d = 1; d < 32; d <<= 1) {
            unsigned x = __shfl_up_sync(0xffffffffu, c, d);
            if (lane >= d) c += x;
        }
        if (lane == 31) s_wsum[wid] = c;
        __syncthreads();
        unsigned off = 0;
#pragma unroll
        for (int j = 0; j < 8; ++j) if (j < wid) off += s_wsum[j];
        c += off;
        if (c >= kk && (c - v) < kk) {
            s_selb = (unsigned)(255 - tid);
            s_kk2  = kk - (c - v);
        }
        __syncthreads();
        prefix |= (s_selb << shift);
        kk = s_kk2;
        __syncthreads();
    }

    // prefix = bits of k-th largest value T; kk = #ties of T to include
    float T = __uint_as_float(prefix);
    float sum = 0.0f;
    for (int idx = tid; idx < P; idx += 256) {
        float x = mine[idx];
        if (__float_as_uint(x) > prefix) sum = __fadd_rn(sum, x);
    }
#pragma unroll
    for (int d = 16; d > 0; d >>= 1) sum += __shfl_down_sync(0xffffffffu, sum, d);
    __shared__ double s_part[8];
    if (lane == 0) s_part[wid] = (double)sum;
    __syncthreads();
    if (tid == 0) {
        double tot = 0.0;
#pragma unroll
        for (int j = 0; j < 8; ++j) tot += s_part[j];
        tot += (double)kk * (double)T;
        atomicAdd(&g_neg_ce, tot);
    }
}

// ---------------- K5: finalize ----------------
__global__ void final_kernel(float* __restrict__ out) {
    int s = 0;
#pragma unroll
    for (int b = 0; b < B; ++b) s += g_num_pos[b];
    double N = (double)s;
    if (N < 1.0) N = 1.0;
    out[0] = (float)(g_loss_l / N);
    out[1] = (float)((g_pos_ce + g_neg_ce) / N);
}

// ---------------- launch ----------------
extern "C" void kernel_launch(void* const* d_in, const int* in_sizes, int n_in,
                              void* d_out, int out_size) {
    const float* loc     = (const float*)d_in[0];
    const float* conf    = (const float*)d_in[1];
    const float* priors  = (const float*)d_in[2];
    const float* targets = (const float*)d_in[3];
    float* out = (float*)d_out;

    init_kernel<<<1, 32>>>();
    match_kernel<<<dim3(NCH, B), 256>>>(priors, targets);
    fix_kernel<<<B, O>>>();
    loss_kernel<<<dim3(P / 256, B), 256>>>(loc, conf, priors, targets);
    select_kernel<<<B, 256>>>();
    final_kernel<<<1, 1>>>(out);
}

// round 2
// speedup vs baseline: 2.3843x; 2.3843x over previous
#include <cuda_runtime.h>
#include <cuda_bf16.h>
#include <math.h>

#define B 32
#define P 32768
#define O 32
#define NCH 16          // chunks per batch in match kernel (P / 2048)
#define PPB 2048        // priors per block (256 threads * 8)
#define THRESH 0.35f
#define LBLK (P / 256)          // loss blocks per batch = 128
#define NPART (LBLK * B)        // 4096 partial slots

// ---------------- scratch (static device globals; no allocation) ----------------
__device__ float g_bt_iou[B * P];     // best-truth IoU per (b,p) (post-fix)
__device__ int   g_bt_idx[B * P];     // best-truth index per (b,p) (post-fix)
__device__ float g_mine [B * P];      // pos ? 0 : ce
__device__ float g_bp_i [B * O * NCH];
__device__ float g_bp_u [B * O * NCH];
__device__ int   g_bp_p [B * O * NCH];
__device__ int    g_num_pos[B];
__device__ float  g_part_l[NPART];
__device__ float  g_part_c[NPART];
__device__ double g_neg_ce;

// ---------------- K0: zero accumulators ----------------
__global__ void init_kernel() {
    int t = threadIdx.x;
    if (t < B) g_num_pos[t] = 0;
    if (t == 0) g_neg_ce = 0.0;
}

// ---------------- K1: match (IoU argmaxes) ----------------
// grid (NCH, B), block 256. Each thread handles 8 priors (stride 256).
__global__ void __launch_bounds__(256) match_kernel(const float* __restrict__ priors,
                                                    const float* __restrict__ targets) {
    const int b     = blockIdx.y;
    const int chunk = blockIdx.x;
    const int tid   = threadIdx.x;
    const int lane  = tid & 31;
    const int wid   = tid >> 5;

    __shared__ float s_tx0[O], s_ty0[O], s_tx1[O], s_ty1[O], s_ta[O];
    __shared__ float s_wi[O][8];
    __shared__ float s_wu[O][8];
    __shared__ int   s_wp[O][8];

    if (tid < O) {
        const float* t = targets + (size_t)(b * O + tid) * 5;
        float x0 = t[0], y0 = t[1], x1 = t[2], y1 = t[3];
        s_tx0[tid] = x0; s_ty0[tid] = y0; s_tx1[tid] = x1; s_ty1[tid] = y1;
        s_ta[tid] = __fmul_rn(__fsub_rn(x1, x0), __fsub_rn(y1, y0));
    }
    __syncthreads();

    const int p0 = chunk * PPB + tid;

    // cache 8 priors in point form + area (area from point-form corners, like reference)
    float px0[8], py0[8], px1[8], py1[8], pa[8];
#pragma unroll
    for (int i = 0; i < 8; ++i) {
        float4 pr = reinterpret_cast<const float4*>(priors)[p0 + i * 256];
        float hw = __fmul_rn(pr.z, 0.5f);
        float hh = __fmul_rn(pr.w, 0.5f);
        px0[i] = __fsub_rn(pr.x, hw);
        py0[i] = __fsub_rn(pr.y, hh);
        px1[i] = __fadd_rn(pr.x, hw);
        py1[i] = __fadd_rn(pr.y, hh);
        pa[i]  = __fmul_rn(__fsub_rn(px1[i], px0[i]), __fsub_rn(py1[i], py0[i]));
    }

    // per-prior running best over o (cross-mult compare; strict > keeps first o)
    float bi[8], bu[8]; int bo[8];
#pragma unroll
    for (int i = 0; i < 8; ++i) { bi[i] = 0.0f; bu[i] = 1.0f; bo[i] = 0; }

    for (int o = 0; o < O; ++o) {
        const float tx0 = s_tx0[o], ty0 = s_ty0[o], tx1 = s_tx1[o], ty1 = s_ty1[o], ta = s_ta[o];
        float ci = -1.0f, cu = 1.0f; int cp = 0x7fffffff;   // per-thread best over p for this o
#pragma unroll
        for (int i = 0; i < 8; ++i) {
            float wx = fmaxf(__fsub_rn(fminf(px1[i], tx1), fmaxf(px0[i], tx0)), 0.0f);
            float wy = fmaxf(__fsub_rn(fminf(py1[i], ty1), fmaxf(py0[i], ty0)), 0.0f);
            float in_ = __fmul_rn(wx, wy);
            float un  = __fsub_rn(__fadd_rn(pa[i], ta), in_);
            // best over o (strict >: first max wins, matching jnp.argmax)
            if (__fmul_rn(in_, bu[i]) > __fmul_rn(bi[i], un)) { bi[i] = in_; bu[i] = un; bo[i] = o; }
            // best over this thread's priors for current o (ascending p; strict > keeps lowest p)
            if (__fmul_rn(in_, cu) > __fmul_rn(ci, un)) { ci = in_; cu = un; cp = p0 + i * 256; }
        }
        // warp argmax over 256 priors (tie -> lower p)
#pragma unroll
        for (int d = 16; d > 0; d >>= 1) {
            float oi = __shfl_down_sync(0xffffffffu, ci, d);
            float ou = __shfl_down_sync(0xffffffffu, cu, d);
            int   op = __shfl_down_sync(0xffffffffu, cp, d);
            float l = __fmul_rn(oi, cu);
            float r = __fmul_rn(ci, ou);
            bool take = (l > r) || (l == r && op < cp);
            if (take) { ci = oi; cu = ou; cp = op; }
        }
        if (lane == 0) { s_wi[o][wid] = ci; s_wu[o][wid] = cu; s_wp[o][wid] = cp; }
    }

    // per-prior results: single IEEE divide for the winner (matches reference rounding)
#pragma unroll
    for (int i = 0; i < 8; ++i) {
        int p = p0 + i * 256;
        g_bt_idx[b * P + p] = bo[i];
        g_bt_iou[b * P + p] = __fdiv_rn(bi[i], bu[i]);
    }

    __syncthreads();
    if (tid < O) {
        int o = tid;
        float ci = s_wi[o][0], cu = s_wu[o][0];
        int   cp = s_wp[o][0];
#pragma unroll
        for (int w = 1; w < 8; ++w) {
            float oi = s_wi[o][w], ou = s_wu[o][w];
            int   op = s_wp[o][w];
            float l = __fmul_rn(oi, cu);
            float r = __fmul_rn(ci, ou);
            if ((l > r) || (l == r && op < cp)) { ci = oi; cu = ou; cp = op; }
        }
        int idx = (b * O + o) * NCH + chunk;
        g_bp_i[idx] = ci; g_bp_u[idx] = cu; g_bp_p[idx] = cp;
    }
}

// ---------------- K2: reduce best-prior per (b,o) + forced-match fix ----------------
__global__ void fix_kernel() {
    const int b = blockIdx.x;
    const int o = threadIdx.x;
    __shared__ int s_bpi[O];

    int base = (b * O + o) * NCH;
    float ci = g_bp_i[base], cu = g_bp_u[base];
    int   cp = g_bp_p[base];
#pragma unroll
    for (int c = 1; c < NCH; ++c) {
        float oi = g_bp_i[base + c], ou = g_bp_u[base + c];
        int   op = g_bp_p[base + c];
        float l = __fmul_rn(oi, cu);
        float r = __fmul_rn(ci, ou);
        if ((l > r) || (l == r && op < cp)) { ci = oi; cu = ou; cp = op; }
    }
    s_bpi[o] = cp;
    __syncthreads();
    if (o == 0) {
        // sequential, ascending o: last-wins on duplicate indices (XLA scatter order)
        for (int j = 0; j < O; ++j) {
            int p = s_bpi[j];
            g_bt_idx[b * P + p] = j;
            g_bt_iou[b * P + p] = 2.0f;
        }
    }
}

// ---------------- K3: per-prior losses (atomic-free block partials) ----------------
__device__ __forceinline__ float smooth_l1(float d) {
    float ad = fabsf(d);
    return (ad < 1.0f) ? __fmul_rn(__fmul_rn(0.5f, d), d) : __fsub_rn(ad, 0.5f);
}

__global__ void __launch_bounds__(256) loss_kernel(const float* __restrict__ loc,
                                                   const float* __restrict__ conf,
                                                   const float* __restrict__ priors,
                                                   const float* __restrict__ targets) {
    const int b = blockIdx.y;
    const int p = blockIdx.x * 256 + threadIdx.x;
    const int lane = threadIdx.x & 31;
    const int wid  = threadIdx.x >> 5;

    __shared__ float s_t[O][4];
    __shared__ float s_lab[O];
    __shared__ float s_ll[8], s_pce[8];
    __shared__ int   s_np[8];
    if (threadIdx.x < O) {
        const float* t = targets + (size_t)(b * O + threadIdx.x) * 5;
        s_t[threadIdx.x][0] = t[0]; s_t[threadIdx.x][1] = t[1];
        s_t[threadIdx.x][2] = t[2]; s_t[threadIdx.x][3] = t[3];
        s_lab[threadIdx.x]  = t[4];
    }
    __syncthreads();

    const int bp = b * P + p;
    const int o  = g_bt_idx[bp];
    const float iou = g_bt_iou[bp];
    const int ct = (iou < THRESH) ? 0 : ((int)s_lab[o] + 1);
    const bool pos = (ct > 0);

    float2 cd = reinterpret_cast<const float2*>(conf)[bp];
    float m  = fmaxf(cd.x, cd.y);
    float mn = fminf(cd.x, cd.y);
    float lse = __fadd_rn(m, __logf(__fadd_rn(1.0f, __expf(__fsub_rn(mn, m)))));
    float picked = (ct == 0) ? cd.x : cd.y;
    float ce = __fsub_rn(lse, picked);

    g_mine[bp] = pos ? 0.0f : ce;

    float ll = 0.0f;
    if (pos) {
        float4 pr = reinterpret_cast<const float4*>(priors)[p];
        float mx0 = s_t[o][0], my0 = s_t[o][1], mx1 = s_t[o][2], my1 = s_t[o][3];
        float lt0 = __fdividef(__fsub_rn(__fmul_rn(__fadd_rn(mx0, mx1), 0.5f), pr.x),
                               __fmul_rn(0.1f, pr.z));
        float lt1 = __fdividef(__fsub_rn(__fmul_rn(__fadd_rn(my0, my1), 0.5f), pr.y),
                               __fmul_rn(0.1f, pr.w));
        float lt2 = __fmul_rn(__logf(__fdividef(__fsub_rn(mx1, mx0), pr.z)), 5.0f);
        float lt3 = __fmul_rn(__logf(__fdividef(__fsub_rn(my1, my0), pr.w)), 5.0f);
        float4 ld = reinterpret_cast<const float4*>(loc)[bp];
        ll = __fadd_rn(__fadd_rn(smooth_l1(__fsub_rn(ld.x, lt0)),
                                 smooth_l1(__fsub_rn(ld.y, lt1))),
                       __fadd_rn(smooth_l1(__fsub_rn(ld.z, lt2)),
                                 smooth_l1(__fsub_rn(ld.w, lt3))));
    }
    float pce = pos ? ce : 0.0f;

#pragma unroll
    for (int d = 16; d > 0; d >>= 1) {
        ll  += __shfl_down_sync(0xffffffffu, ll, d);
        pce += __shfl_down_sync(0xffffffffu, pce, d);
    }
    unsigned bal = __ballot_sync(0xffffffffu, pos);
    if (lane == 0) { s_ll[wid] = ll; s_pce[wid] = pce; s_np[wid] = __popc(bal); }
    __syncthreads();
    if (threadIdx.x == 0) {
        float tl = 0.0f, tc = 0.0f; int tn = 0;
#pragma unroll
        for (int w = 0; w < 8; ++w) { tl += s_ll[w]; tc += s_pce[w]; tn += s_np[w]; }
        int slot = b * LBLK + blockIdx.x;
        g_part_l[slot] = tl;
        g_part_c[slot] = tc;
        if (tn) atomicAdd(&g_num_pos[b], tn);
    }
}

// ---------------- K4: per-batch top-k sum of mine (exact radix select) ----------------
// grid B, block 1024. float4 loads for MLP.
__global__ void __launch_bounds__(1024) select_kernel() {
    const int b = blockIdx.x;
    const int tid = threadIdx.x;
    const int lane = tid & 31;
    const int wid  = tid >> 5;

    int np = g_num_pos[b];
    long long kll = (long long)7 * np;
    int k = (kll < (P - 1)) ? (int)kll : (P - 1);
    if (k <= 0) return;

    const float4* mine4 = reinterpret_cast<const float4*>(g_mine + (size_t)b * P);

    __shared__ unsigned s_hist[256];
    __shared__ unsigned s_wsum[8];
    __shared__ unsigned s_selb;
    __shared__ unsigned s_kk2;
    __shared__ double   s_part[32];

    unsigned prefix = 0;
    unsigned kk = (unsigned)k;

    for (int pass = 0; pass < 4; ++pass) {
        const int shift = 24 - 8 * pass;
        if (tid < 256) s_hist[tid] = 0;
        __syncthreads();
        unsigned himask = (pass == 0) ? 0u : (0xFFFFFFFFu << (shift + 8));
#pragma unroll
        for (int it = 0; it < 8; ++it) {
            float4 x = mine4[tid + it * 1024];
            unsigned u0 = __float_as_uint(x.x), u1 = __float_as_uint(x.y);
            unsigned u2 = __float_as_uint(x.z), u3 = __float_as_uint(x.w);
            if ((u0 & himask) == prefix) atomicAdd(&s_hist[(u0 >> shift) & 255u], 1u);
            if ((u1 & himask) == prefix) atomicAdd(&s_hist[(u1 >> shift) & 255u], 1u);
            if ((u2 & himask) == prefix) atomicAdd(&s_hist[(u2 >> shift) & 255u], 1u);
            if ((u3 & himask) == prefix) atomicAdd(&s_hist[(u3 >> shift) & 255u], 1u);
        }
        __syncthreads();
        // suffix-cumulative from top bin (first 256 threads)
        unsigned v = (tid < 256) ? s_hist[255 - tid] : 0u;
        unsigned c = v;
#pragma unroll
        for (int d = 1; d < 32; d <<= 1) {
            unsigned x = __shfl_up_sync(0xffffffffu, c, d);
            if (lane >= d) c += x;
        }
        if (tid < 256 && lane == 31) s_wsum[wid] = c;
        __syncthreads();
        if (tid < 256) {
            unsigned off = 0;
#pragma unroll
            for (int j = 0; j < 8; ++j) if (j < wid) off += s_wsum[j];
            c += off;
            if (c >= kk && (c - v) < kk) {
                s_selb = (unsigned)(255 - tid);
                s_kk2  = kk - (c - v);
            }
        }
        __syncthreads();
        prefix |= (s_selb << shift);
        kk = s_kk2;
        __syncthreads();
    }

    // prefix = bits of k-th largest value T; kk = #ties of T to include
    float T = __uint_as_float(prefix);
    float sum = 0.0f;
#pragma unroll
    for (int it = 0; it < 8; ++it) {
        float4 x = mine4[tid + it * 1024];
        if (__float_as_uint(x.x) > prefix) sum = __fadd_rn(sum, x.x);
        if (__float_as_uint(x.y) > prefix) sum = __fadd_rn(sum, x.y);
        if (__float_as_uint(x.z) > prefix) sum = __fadd_rn(sum, x.z);
        if (__float_as_uint(x.w) > prefix) sum = __fadd_rn(sum, x.w);
    }
#pragma unroll
    for (int d = 16; d > 0; d >>= 1) sum += __shfl_down_sync(0xffffffffu, sum, d);
    if (lane == 0) s_part[wid] = (double)sum;
    __syncthreads();
    if (tid == 0) {
        double tot = 0.0;
#pragma unroll
        for (int j = 0; j < 32; ++j) tot += s_part[j];
        tot += (double)kk * (double)T;
        atomicAdd(&g_neg_ce, tot);
    }
}

// ---------------- K5: finalize (deterministic partial reduction) ----------------
__global__ void __launch_bounds__(1024) final_kernel(float* __restrict__ out) {
    const int tid = threadIdx.x;
    const int lane = tid & 31;
    const int wid  = tid >> 5;
    __shared__ double s_l[32], s_c[32];

    double l = 0.0, c = 0.0;
#pragma unroll
    for (int it = 0; it < NPART / 1024; ++it) {
        l += (double)g_part_l[tid + it * 1024];
        c += (double)g_part_c[tid + it * 1024];
    }
#pragma unroll
    for (int d = 16; d > 0; d >>= 1) {
        l += __shfl_down_sync(0xffffffffu, l, d);
        c += __shfl_down_sync(0xffffffffu, c, d);
    }
    if (lane == 0) { s_l[wid] = l; s_c[wid] = c; }
    __syncthreads();
    if (tid == 0) {
        double tl = 0.0, tc = 0.0;
#pragma unroll
        for (int j = 0; j < 32; ++j) { tl += s_l[j]; tc += s_c[j]; }
        int s = 0;
#pragma unroll
        for (int b = 0; b < B; ++b) s += g_num_pos[b];
        double N = (double)s;
        if (N < 1.0) N = 1.0;
        out[0] = (float)(tl / N);
        out[1] = (float)((tc + g_neg_ce) / N);
    }
}

// ---------------- launch ----------------
extern "C" void kernel_launch(void* const* d_in, const int* in_sizes, int n_in,
                              void* d_out, int out_size) {
    const float* loc     = (const float*)d_in[0];
    const float* conf    = (const float*)d_in[1];
    const float* priors  = (const float*)d_in[2];
    const float* targets = (const float*)d_in[3];
    float* out = (float*)d_out;

    init_kernel<<<1, 32>>>();
    match_kernel<<<dim3(NCH, B), 256>>>(priors, targets);
    fix_kernel<<<B, O>>>();
    loss_kernel<<<dim3(LBLK, B), 256>>>(loc, conf, priors, targets);
    select_kernel<<<B, 1024>>>();
    final_kernel<<<1, 1024>>>(out);
}

// round 3
// speedup vs baseline: 2.6403x; 1.1074x over previous
#include <cuda_runtime.h>
#include <cuda_bf16.h>
#include <math.h>

#define B 32
#define P 32768
#define O 32
#define NCH 16          // chunks per batch in match kernel (P / 2048)
#define PPB 2048        // priors per block (256 threads * 8)
#define THRESH 0.35f
#define LBLK 128                // loss blocks per batch
#define NPART (LBLK * B)        // 4096 partial slots

// ---------------- scratch (static device globals; no allocation) ----------------
__device__ float2 g_bt  [B * P];          // (iou, idx-as-float) per (b,p)
__device__ float  g_mine[B * P];          // pos ? 0 : ce
__device__ float  g_bp_q[B * O * NCH];
__device__ int    g_bp_p[B * O * NCH];
__device__ int    g_num_pos[B];
__device__ float  g_part_l[NPART];
__device__ float  g_part_c[NPART];
__device__ double g_neg_b[B];
__device__ int    g_done;

// ---------------- K1: match (IoU argmaxes via fast-quotient compare) ----------------
// grid (NCH, B), block 256. Each thread handles 8 priors (stride 256).
__global__ void __launch_bounds__(256) match_kernel(const float* __restrict__ priors,
                                                    const float* __restrict__ targets) {
    const int b     = blockIdx.y;
    const int chunk = blockIdx.x;
    const int tid   = threadIdx.x;
    const int lane  = tid & 31;
    const int wid   = tid >> 5;

    __shared__ float s_tx0[O], s_ty0[O], s_tx1[O], s_ty1[O], s_ta[O];
    __shared__ float s_wq[O][8];
    __shared__ int   s_wp[O][8];

    // fold init_kernel in: one block zeroes the cross-kernel accumulators
    if (b == 0 && chunk == 0) {
        if (tid < B) g_num_pos[tid] = 0;
        if (tid == 0) g_done = 0;
    }

    if (tid < O) {
        const float* t = targets + (size_t)(b * O + tid) * 5;
        float x0 = t[0], y0 = t[1], x1 = t[2], y1 = t[3];
        s_tx0[tid] = x0; s_ty0[tid] = y0; s_tx1[tid] = x1; s_ty1[tid] = y1;
        s_ta[tid] = __fmul_rn(__fsub_rn(x1, x0), __fsub_rn(y1, y0));
    }
    __syncthreads();

    const int p0 = chunk * PPB + tid;

    // cache 8 priors in point form + area (exact _rn ops, matching reference)
    float px0[8], py0[8], px1[8], py1[8], pa[8];
#pragma unroll
    for (int i = 0; i < 8; ++i) {
        float4 pr = reinterpret_cast<const float4*>(priors)[p0 + i * 256];
        float hw = __fmul_rn(pr.z, 0.5f);
        float hh = __fmul_rn(pr.w, 0.5f);
        px0[i] = __fsub_rn(pr.x, hw);
        py0[i] = __fsub_rn(pr.y, hh);
        px1[i] = __fadd_rn(pr.x, hw);
        py1[i] = __fadd_rn(pr.y, hh);
        pa[i]  = __fmul_rn(__fsub_rn(px1[i], px0[i]), __fsub_rn(py1[i], py0[i]));
    }

    // per-prior running best over o (strict > keeps first o, like jnp.argmax)
    float bq[8]; int bo[8];
#pragma unroll
    for (int i = 0; i < 8; ++i) { bq[i] = 0.0f; bo[i] = 0; }

    for (int o = 0; o < O; ++o) {
        const float tx0 = s_tx0[o], ty0 = s_ty0[o], tx1 = s_tx1[o], ty1 = s_ty1[o], ta = s_ta[o];
        float cq = -1.0f; int cp = 0;   // per-thread best over p for this o
#pragma unroll
        for (int i = 0; i < 8; ++i) {
            float wx = fmaxf(fminf(px1[i], tx1) - fmaxf(px0[i], tx0), 0.0f);
            float wy = fmaxf(fminf(py1[i], ty1) - fmaxf(py0[i], ty0), 0.0f);
            float in_ = wx * wy;
            float un  = (pa[i] + ta) - in_;      // > 0 always
            float q   = __fdividef(in_, un);     // MUFU rcp + mul (approx, compare-only)
            if (q > bq[i]) { bq[i] = q; bo[i] = o; }
            if (q > cq)    { cq = q; cp = p0 + i * 256; }   // ascending p: first max kept
        }
        // warp argmax over 256 priors (tie -> lower p)
#pragma unroll
        for (int d = 16; d > 0; d >>= 1) {
            float oq = __shfl_down_sync(0xffffffffu, cq, d);
            int   op = __shfl_down_sync(0xffffffffu, cp, d);
            if (oq > cq || (oq == cq && op < cp)) { cq = oq; cp = op; }
        }
        if (lane == 0) { s_wq[o][wid] = cq; s_wp[o][wid] = cp; }
    }

    // per-prior output: recompute winner's IoU with exact IEEE ops (matches reference)
#pragma unroll
    for (int i = 0; i < 8; ++i) {
        int o = bo[i];
        float tx0 = s_tx0[o], ty0 = s_ty0[o], tx1 = s_tx1[o], ty1 = s_ty1[o], ta = s_ta[o];
        float wx = fmaxf(__fsub_rn(fminf(px1[i], tx1), fmaxf(px0[i], tx0)), 0.0f);
        float wy = fmaxf(__fsub_rn(fminf(py1[i], ty1), fmaxf(py0[i], ty0)), 0.0f);
        float in_ = __fmul_rn(wx, wy);
        float un  = __fsub_rn(__fadd_rn(pa[i], ta), in_);
        g_bt[b * P + p0 + i * 256] = make_float2(__fdiv_rn(in_, un), __int_as_float(o));
    }

    __syncthreads();
    if (tid < O) {
        int o = tid;
        float cq = s_wq[o][0]; int cp = s_wp[o][0];
#pragma unroll
        for (int w = 1; w < 8; ++w) {
            float oq = s_wq[o][w]; int op = s_wp[o][w];
            if (oq > cq || (oq == cq && op < cp)) { cq = oq; cp = op; }
        }
        int idx = (b * O + o) * NCH + chunk;
        g_bp_q[idx] = cq; g_bp_p[idx] = cp;
    }
}

// ---------------- K2: reduce best-prior per (b,o) + forced-match fix ----------------
__global__ void fix_kernel() {
    const int b = blockIdx.x;
    const int o = threadIdx.x;
    __shared__ int s_bpi[O];

    int base = (b * O + o) * NCH;
    float cq = g_bp_q[base]; int cp = g_bp_p[base];
#pragma unroll
    for (int c = 1; c < NCH; ++c) {
        float oq = g_bp_q[base + c]; int op = g_bp_p[base + c];
        if (oq > cq || (oq == cq && op < cp)) { cq = oq; cp = op; }
    }
    s_bpi[o] = cp;
    __syncthreads();
    if (o == 0) {
        // sequential, ascending o: last-wins on duplicate indices (XLA scatter order)
        for (int j = 0; j < O; ++j) {
            int p = s_bpi[j];
            g_bt[b * P + p] = make_float2(2.0f, __int_as_float(j));
        }
    }
}

// ---------------- K3: per-prior losses (atomic-free block partials) ----------------
__device__ __forceinline__ float smooth_l1(float d) {
    float ad = fabsf(d);
    return (ad < 1.0f) ? __fmul_rn(__fmul_rn(0.5f, d), d) : __fsub_rn(ad, 0.5f);
}

__global__ void __launch_bounds__(256) loss_kernel(const float* __restrict__ loc,
                                                   const float* __restrict__ conf,
                                                   const float* __restrict__ priors,
                                                   const float* __restrict__ targets) {
    const int b = blockIdx.y;
    const int p = blockIdx.x * 256 + threadIdx.x;
    const int lane = threadIdx.x & 31;
    const int wid  = threadIdx.x >> 5;

    __shared__ float s_t[O][4];
    __shared__ float s_lab[O];
    __shared__ float s_ll[8], s_pce[8];
    __shared__ int   s_np[8];
    if (threadIdx.x < O) {
        const float* t = targets + (size_t)(b * O + threadIdx.x) * 5;
        s_t[threadIdx.x][0] = t[0]; s_t[threadIdx.x][1] = t[1];
        s_t[threadIdx.x][2] = t[2]; s_t[threadIdx.x][3] = t[3];
        s_lab[threadIdx.x]  = t[4];
    }
    __syncthreads();

    const int bp = b * P + p;
    float2 bt = g_bt[bp];
    const int o = __float_as_int(bt.y);
    const int ct = (bt.x < THRESH) ? 0 : ((int)s_lab[o] + 1);
    const bool pos = (ct > 0);

    float2 cd = reinterpret_cast<const float2*>(conf)[bp];
    float m  = fmaxf(cd.x, cd.y);
    float mn = fminf(cd.x, cd.y);
    float lse = __fadd_rn(m, __logf(__fadd_rn(1.0f, __expf(__fsub_rn(mn, m)))));
    float picked = (ct == 0) ? cd.x : cd.y;
    float ce = __fsub_rn(lse, picked);

    g_mine[bp] = pos ? 0.0f : ce;

    unsigned bal = __ballot_sync(0xffffffffu, pos);
    float ll = 0.0f, pce = 0.0f;
    if (bal) {   // warp-uniform skip: fully-negative warps avoid encode entirely
        if (pos) {
            float4 pr = reinterpret_cast<const float4*>(priors)[p];
            float mx0 = s_t[o][0], my0 = s_t[o][1], mx1 = s_t[o][2], my1 = s_t[o][3];
            float lt0 = __fdividef(__fsub_rn(__fmul_rn(__fadd_rn(mx0, mx1), 0.5f), pr.x),
                                   __fmul_rn(0.1f, pr.z));
            float lt1 = __fdividef(__fsub_rn(__fmul_rn(__fadd_rn(my0, my1), 0.5f), pr.y),
                                   __fmul_rn(0.1f, pr.w));
            float lt2 = __fmul_rn(__logf(__fdividef(__fsub_rn(mx1, mx0), pr.z)), 5.0f);
            float lt3 = __fmul_rn(__logf(__fdividef(__fsub_rn(my1, my0), pr.w)), 5.0f);
            float4 ld = reinterpret_cast<const float4*>(loc)[bp];
            ll = __fadd_rn(__fadd_rn(smooth_l1(__fsub_rn(ld.x, lt0)),
                                     smooth_l1(__fsub_rn(ld.y, lt1))),
                           __fadd_rn(smooth_l1(__fsub_rn(ld.z, lt2)),
                                     smooth_l1(__fsub_rn(ld.w, lt3))));
            pce = ce;
        }
#pragma unroll
        for (int d = 16; d > 0; d >>= 1) {
            ll  += __shfl_down_sync(0xffffffffu, ll, d);
            pce += __shfl_down_sync(0xffffffffu, pce, d);
        }
    }
    if (lane == 0) { s_ll[wid] = ll; s_pce[wid] = pce; s_np[wid] = __popc(bal); }
    __syncthreads();
    if (threadIdx.x == 0) {
        float tl = 0.0f, tc = 0.0f; int tn = 0;
#pragma unroll
        for (int w = 0; w < 8; ++w) { tl += s_ll[w]; tc += s_pce[w]; tn += s_np[w]; }
        int slot = b * LBLK + blockIdx.x;
        g_part_l[slot] = tl;
        g_part_c[slot] = tc;
        if (tn) atomicAdd(&g_num_pos[b], tn);
    }
}

// ---------------- K4: per-batch top-k sum (radix select) + fused finalize ----------------
__global__ void __launch_bounds__(1024) select_kernel(float* __restrict__ out) {
    const int b = blockIdx.x;
    const int tid = threadIdx.x;
    const int lane = tid & 31;
    const int wid  = tid >> 5;

    __shared__ unsigned s_hist[256];
    __shared__ unsigned s_wsum[8];
    __shared__ unsigned s_selb;
    __shared__ unsigned s_kk2;
    __shared__ double   s_part[32];
    __shared__ int      s_ticket;

    int np = g_num_pos[b];
    long long kll = (long long)7 * np;
    int k = (kll < (P - 1)) ? (int)kll : (P - 1);

    double myneg = 0.0;
    if (k > 0) {
        const float4* mine4 = reinterpret_cast<const float4*>(g_mine + (size_t)b * P);
        unsigned prefix = 0;
        unsigned kk = (unsigned)k;

        for (int pass = 0; pass < 4; ++pass) {
            const int shift = 24 - 8 * pass;
            if (tid < 256) s_hist[tid] = 0;
            __syncthreads();
            unsigned himask = (pass == 0) ? 0u : (0xFFFFFFFFu << (shift + 8));
#pragma unroll
            for (int it = 0; it < 8; ++it) {
                float4 x = mine4[tid + it * 1024];
                unsigned u0 = __float_as_uint(x.x), u1 = __float_as_uint(x.y);
                unsigned u2 = __float_as_uint(x.z), u3 = __float_as_uint(x.w);
                if ((u0 & himask) == prefix) atomicAdd(&s_hist[(u0 >> shift) & 255u], 1u);
                if ((u1 & himask) == prefix) atomicAdd(&s_hist[(u1 >> shift) & 255u], 1u);
                if ((u2 & himask) == prefix) atomicAdd(&s_hist[(u2 >> shift) & 255u], 1u);
                if ((u3 & himask) == prefix) atomicAdd(&s_hist[(u3 >> shift) & 255u], 1u);
            }
            __syncthreads();
            unsigned v = (tid < 256) ? s_hist[255 - tid] : 0u;
            unsigned c = v;
#pragma unroll
            for (int d = 1; d < 32; d <<= 1) {
                unsigned x = __shfl_up_sync(0xffffffffu, c, d);
                if (lane >= d) c += x;
            }
            if (tid < 256 && lane == 31) s_wsum[wid] = c;
            __syncthreads();
            if (tid < 256) {
                unsigned off = 0;
#pragma unroll
                for (int j = 0; j < 8; ++j) if (j < wid) off += s_wsum[j];
                c += off;
                if (c >= kk && (c - v) < kk) {
                    s_selb = (unsigned)(255 - tid);
                    s_kk2  = kk - (c - v);
                }
            }
            __syncthreads();
            prefix |= (s_selb << shift);
            kk = s_kk2;
            __syncthreads();
        }

        float T = __uint_as_float(prefix);
        float sum = 0.0f;
#pragma unroll
        for (int it = 0; it < 8; ++it) {
            float4 x = mine4[tid + it * 1024];
            if (__float_as_uint(x.x) > prefix) sum = __fadd_rn(sum, x.x);
            if (__float_as_uint(x.y) > prefix) sum = __fadd_rn(sum, x.y);
            if (__float_as_uint(x.z) > prefix) sum = __fadd_rn(sum, x.z);
            if (__float_as_uint(x.w) > prefix) sum = __fadd_rn(sum, x.w);
        }
#pragma unroll
        for (int d = 16; d > 0; d >>= 1) sum += __shfl_down_sync(0xffffffffu, sum, d);
        if (lane == 0) s_part[wid] = (double)sum;
        __syncthreads();
        if (tid == 0) {
            double tot = 0.0;
#pragma unroll
            for (int j = 0; j < 32; ++j) tot += s_part[j];
            myneg = tot + (double)kk * (double)T;
        }
    }

    // publish per-batch result, take ticket; last block finalizes
    if (tid == 0) {
        g_neg_b[b] = myneg;
        __threadfence();
        s_ticket = atomicAdd(&g_done, 1);
    }
    __syncthreads();
    if (s_ticket != B - 1) return;

    double l = 0.0, c = 0.0;
#pragma unroll
    for (int it = 0; it < NPART / 1024; ++it) {
        l += (double)g_part_l[tid + it * 1024];
        c += (double)g_part_c[tid + it * 1024];
    }
#pragma unroll
    for (int d = 16; d > 0; d >>= 1) {
        l += __shfl_down_sync(0xffffffffu, l, d);
        c += __shfl_down_sync(0xffffffffu, c, d);
    }
    __shared__ double s_l2[32], s_c2[32];
    if (lane == 0) { s_l2[wid] = l; s_c2[wid] = c; }
    __syncthreads();
    if (tid == 0) {
        double tl = 0.0, tc = 0.0;
#pragma unroll
        for (int j = 0; j < 32; ++j) { tl += s_l2[j]; tc += s_c2[j]; }
        double tneg = 0.0;
        int s = 0;
#pragma unroll
        for (int j = 0; j < B; ++j) {
            tneg += __ldcg(&g_neg_b[j]);     // L2 reads: other blocks' same-launch writes
            s += g_num_pos[j];
        }
        double N = (double)s;
        if (N < 1.0) N = 1.0;
        out[0] = (float)(tl / N);
        out[1] = (float)((tc + tneg) / N);
    }
}

// ---------------- launch ----------------
extern "C" void kernel_launch(void* const* d_in, const int* in_sizes, int n_in,
                              void* d_out, int out_size) {
    const float* loc     = (const float*)d_in[0];
    const float* conf    = (const float*)d_in[1];
    const float* priors  = (const float*)d_in[2];
    const float* targets = (const float*)d_in[3];
    float* out = (float*)d_out;

    match_kernel<<<dim3(NCH, B), 256>>>(priors, targets);
    fix_kernel<<<B, O>>>();
    loss_kernel<<<dim3(LBLK, B), 256>>>(loc, conf, priors, targets);
    select_kernel<<<B, 1024>>>(out);
}